// round 5
// baseline (speedup 1.0000x reference)
#include <cuda_runtime.h>
#include <cuda_bf16.h>

// DeformableConvLayer: B=4, H=W=256, C=64, K=3x3, UNITS=1.
// Two-phase algorithm:
//   Phase 1: P_k[pix] = <input[pix,:], kern[k,:]>  (dense streaming contraction,
//            packed fma.rn.f32x2 to halve FFMA issue -> DRAM-bound)
//   Phase 2: out[pix] = bias + sum_k gather(P_k, deformed tap coords)
//            (staged loads: 9 mask gathers in flight, then 9 plane gathers)

namespace {

constexpr int Hc = 256;
constexpr int Wc = 256;
constexpr int PIX = 4 * Hc * Wc;               // 262144

__device__ float g_P[9 * PIX];                 // 9.4 MB tap-plane scratch

__device__ __forceinline__ unsigned long long fma2(unsigned long long a,
                                                   unsigned long long b,
                                                   unsigned long long c)
{
    unsigned long long d;
    asm("fma.rn.f32x2 %0, %1, %2, %3;" : "=l"(d) : "l"(a), "l"(b), "l"(c));
    return d;
}

// ---------------- Phase 1: 9-way channel contraction ----------------
constexpr int P1_T = 128;

__global__ __launch_bounds__(P1_T)
void dcn_phase1(const float* __restrict__ input,   // [PIX, 64]
                const float* __restrict__ kern)    // [9, 64]
{
    __shared__ float4 in_s[P1_T * 16];   // [pixel][c4 ^ (pixel&15)] swizzled
    __shared__ float4 w_s[9 * 16];

    const int t = threadIdx.x;
    const int pixbase = blockIdx.x * P1_T;

    for (int i = t; i < 9 * 16; i += P1_T)
        w_s[i] = reinterpret_cast<const float4*>(kern)[i];

    const float4* in4 = reinterpret_cast<const float4*>(input) + (size_t)pixbase * 16;
#pragma unroll
    for (int i = 0; i < 16; i++) {
        const int g  = i * P1_T + t;
        const int p  = g >> 4;
        const int c4 = g & 15;
        in_s[p * 16 + (c4 ^ (p & 15))] = in4[g];
    }
    __syncthreads();

    unsigned long long acc2[9];
#pragma unroll
    for (int k = 0; k < 9; k++) acc2[k] = 0ull;

#pragma unroll
    for (int c4 = 0; c4 < 16; c4++) {
        // two packed f32x2 values per float4; adjacent floats are already packed
        const ulonglong2 v = *reinterpret_cast<const ulonglong2*>(
                                 &in_s[t * 16 + (c4 ^ (t & 15))]);
#pragma unroll
        for (int k = 0; k < 9; k++) {
            const ulonglong2 wv = *reinterpret_cast<const ulonglong2*>(&w_s[k * 16 + c4]);
            acc2[k] = fma2(v.x, wv.x, acc2[k]);
            acc2[k] = fma2(v.y, wv.y, acc2[k]);
        }
    }

#pragma unroll
    for (int k = 0; k < 9; k++) {
        float lo, hi;
        asm("mov.b64 {%0, %1}, %2;" : "=f"(lo), "=f"(hi) : "l"(acc2[k]));
        g_P[k * PIX + pixbase + t] = lo + hi;
    }
}

// ---------------- Phase 2: deformable scalar gather ----------------
constexpr int P2_T = 256;

__global__ __launch_bounds__(P2_T)
void dcn_phase2(const float* __restrict__ mask,     // [256,256]
                const float* __restrict__ offset,   // [PIX,18]
                const float* __restrict__ bias,
                float* __restrict__ out)            // [PIX]
{
    __shared__ float soff[P2_T * 18];    // 18 KB
    __shared__ float smask[3 * 256];     // base-mask rows h-2..h

    const int t = threadIdx.x;
    const int pixbase = blockIdx.x * P2_T;   // one image row per block
    const int b = pixbase >> 16;
    const int h = (pixbase >> 8) & 255;
    const int w = t;

    {   // stage offsets: 1152 float4, coalesced
        const float4* off4 = reinterpret_cast<const float4*>(offset + (size_t)pixbase * 18);
        float4* soff4 = reinterpret_cast<float4*>(soff);
#pragma unroll
        for (int i = 0; i < 4; i++)
            soff4[i * P2_T + t] = off4[i * P2_T + t];
        if (t < 1152 - 4 * P2_T)
            soff4[4 * P2_T + t] = off4[4 * P2_T + t];
    }
#pragma unroll
    for (int r = 0; r < 3; r++) {
        const int row = h - 2 + r;
        smask[r * 256 + t] = (row >= 0) ? mask[row * Wc + t] : 0.0f;
    }
    __syncthreads();

    // ---- stage A: coords + base mask + 9 independent offset-mask gathers ----
    float yoffv[9], xoffv[9], pmask[9], pmoff[9];
    int   yiv[9], xiv[9];
#pragma unroll
    for (int k = 0; k < 9; k++) {
        const int ky = k / 3;
        const int kx = k - ky * 3;
        const int yb = h + ky - 1;
        const int xb = w + kx - 1;
        const bool inb = (yb >= 0) & (yb < Hc) & (xb >= 0) & (xb < Wc);
        const int yi = inb ? yb : 0;
        const int xi = inb ? xb : 0;
        yiv[k] = yi;  xiv[k] = xi;

        const float2 off2 = *reinterpret_cast<const float2*>(&soff[t * 18 + 2 * k]);
        yoffv[k] = off2.x;
        xoffv[k] = off2.y;

        pmask[k] = (inb & (yb >= 1) & (xb >= 1)) ? smask[ky * 256 + (w + kx - 2)] : 0.0f;

        int yo = (int)floorf((float)yi + off2.x);
        int xo = (int)floorf((float)xi + off2.y);
        yo = min(max(yo, 0), Hc + 1);
        xo = min(max(xo, 0), Wc + 1);
        const bool mv = (yo >= 1) & (yo <= Hc) & (xo >= 1) & (xo <= Wc);
        pmoff[k] = mv ? mask[(yo - 1) * Wc + (xo - 1)] : 0.0f;   // batched LDGs
    }

    // ---- stage B: final coords + 9 independent plane gathers ----
    float pv[9];
#pragma unroll
    for (int k = 0; k < 9; k++) {
        const float diff = (pmask[k] != pmoff[k]) ? 1.0f : 0.0f;
        const float yf = fminf(fmaxf((float)yiv[k] + yoffv[k] * diff, 0.0f), 255.0f);
        const float xf = fminf(fmaxf((float)xiv[k] + xoffv[k] * diff, 0.0f), 255.0f);
        const int y0 = (int)floorf(yf);
        const int x0 = (int)floorf(xf);
        // padded-input sample: zero when y0==0 || x0==0
        const bool valid = (y0 >= 1) & (x0 >= 1);
        pv[k] = valid ? g_P[k * PIX + b * (Hc * Wc) + (y0 - 1) * Wc + (x0 - 1)] : 0.0f;
    }

    // ---- stage C: sum ----
    float acc = __ldg(bias);
#pragma unroll
    for (int k = 0; k < 9; k++) acc += pv[k];

    out[pixbase + t] = acc;
}

} // namespace

extern "C" void kernel_launch(void* const* d_in, const int* in_sizes, int n_in,
                              void* d_out, int out_size)
{
    const float* input  = (const float*)d_in[0];   // [4,256,256,64]
    const float* mask   = (const float*)d_in[1];   // [1,256,256,1]
    const float* offset = (const float*)d_in[2];   // [4,256,256,18]
    const float* kern   = (const float*)d_in[3];   // [3,3,64,1]
    const float* bias   = (const float*)d_in[4];   // [1]
    float* out = (float*)d_out;

    dcn_phase1<<<PIX / P1_T, P1_T>>>(input, kern);
    dcn_phase2<<<PIX / P2_T, P2_T>>>(mask, offset, bias, out);
}

// round 6
// speedup vs baseline: 1.1069x; 1.1069x over previous
#include <cuda_runtime.h>
#include <cuda_bf16.h>

// DeformableConvLayer: B=4, H=W=256, C=64, K=3x3, UNITS=1.
//   Phase 1: P_k[pix] = <input[pix,:], kern[k,:]>  (dense streaming; channel-split
//            smem tiles for 12 blocks/SM; cp.async staging; packed f32x2 FMA)
//   Phase 2: out = bias + sum_k select(mask-diff, P_k@offset-coords, P_k@base-tap)
//            Both candidates computed up front -> ONE latency wave of 18
//            independent gathers; base-tap values come from a coalesced smem
//            stage of the 9 needed plane rows.

namespace {

constexpr int Hc = 256;
constexpr int Wc = 256;
constexpr int PIX = 4 * Hc * Wc;               // 262144

__device__ float g_P[9 * PIX];                 // 9.4 MB tap-plane scratch

__device__ __forceinline__ unsigned long long fma2(unsigned long long a,
                                                   unsigned long long b,
                                                   unsigned long long c)
{
    unsigned long long d;
    asm("fma.rn.f32x2 %0, %1, %2, %3;" : "=l"(d) : "l"(a), "l"(b), "l"(c));
    return d;
}

// ---------------- Phase 1: 9-way channel contraction ----------------
// 128 pixels/block; channels processed in 2 halves of 8 float4 -> 16KB smem.
constexpr int P1_T = 128;

__global__ __launch_bounds__(P1_T)
void dcn_phase1(const float* __restrict__ input,   // [PIX, 64]
                const float* __restrict__ kern)    // [9, 64]
{
    __shared__ float4 in_s[P1_T * 8];    // 16 KB, [pixel][c4 ^ (pixel&7)]
    __shared__ float4 w_s[9 * 16];       // 2.3 KB

    const int t = threadIdx.x;
    const int pixbase = blockIdx.x * P1_T;

    for (int i = t; i < 9 * 16; i += P1_T)
        w_s[i] = reinterpret_cast<const float4*>(kern)[i];

    unsigned long long acc2[9];
#pragma unroll
    for (int k = 0; k < 9; k++) acc2[k] = 0ull;

    const float4* in4 = reinterpret_cast<const float4*>(input) + (size_t)pixbase * 16;

#pragma unroll
    for (int half = 0; half < 2; half++) {
        // stage 8 float4 per thread via cp.async (coalesced global, swizzled smem)
#pragma unroll
        for (int i = 0; i < 8; i++) {
            const int g  = i * P1_T + t;       // 0..1023
            const int p  = g >> 3;             // pixel 0..127
            const int c4 = g & 7;              // 0..7 within half
            const float4* src = &in4[(size_t)p * 16 + half * 8 + c4];
            float4* dst = &in_s[p * 8 + (c4 ^ (p & 7))];
            const unsigned sdst = (unsigned)__cvta_generic_to_shared(dst);
            asm volatile("cp.async.cg.shared.global [%0], [%1], 16;\n"
                         :: "r"(sdst), "l"(src));
        }
        asm volatile("cp.async.commit_group;\n");
        asm volatile("cp.async.wait_group 0;\n" ::: "memory");
        __syncthreads();

#pragma unroll
        for (int c4 = 0; c4 < 8; c4++) {
            const ulonglong2 v = *reinterpret_cast<const ulonglong2*>(
                                     &in_s[t * 8 + (c4 ^ (t & 7))]);
#pragma unroll
            for (int k = 0; k < 9; k++) {
                const ulonglong2 wv = *reinterpret_cast<const ulonglong2*>(
                                          &w_s[k * 16 + half * 8 + c4]);
                acc2[k] = fma2(v.x, wv.x, acc2[k]);
                acc2[k] = fma2(v.y, wv.y, acc2[k]);
            }
        }
        __syncthreads();   // tile reused next half
    }

#pragma unroll
    for (int k = 0; k < 9; k++) {
        float lo, hi;
        asm("mov.b64 {%0, %1}, %2;" : "=f"(lo), "=f"(hi) : "l"(acc2[k]));
        g_P[k * PIX + pixbase + t] = lo + hi;
    }
}

// ---------------- Phase 2: one-wave deformable select-gather ----------------
constexpr int P2_T = 256;

__global__ __launch_bounds__(P2_T)
void dcn_phase2(const float* __restrict__ mask,     // [256,256]
                const float* __restrict__ offset,   // [PIX,18]
                const float* __restrict__ bias,
                float* __restrict__ out)            // [PIX]
{
    __shared__ float soff[P2_T * 18];    // 18 KB offsets for this row
    __shared__ float smask[3 * 256];     // base-mask rows h-2..h
    __shared__ float sP[9 * 256];        // base-tap P rows: plane k, row h+ky-2

    const int t = threadIdx.x;
    const int pixbase = blockIdx.x * P2_T;   // one image row per block
    const int b = pixbase >> 16;
    const int h = (pixbase >> 8) & 255;
    const int w = t;
    const float* Pbase = g_P + (size_t)b * (Hc * Wc);

    {   // stage offsets: 1152 float4, coalesced
        const float4* off4 = reinterpret_cast<const float4*>(offset + (size_t)pixbase * 18);
        float4* soff4 = reinterpret_cast<float4*>(soff);
#pragma unroll
        for (int i = 0; i < 4; i++)
            soff4[i * P2_T + t] = off4[i * P2_T + t];
        if (t < 1152 - 4 * P2_T)
            soff4[4 * P2_T + t] = off4[4 * P2_T + t];
    }
#pragma unroll
    for (int r = 0; r < 3; r++) {
        const int row = h - 2 + r;
        smask[r * 256 + t] = (row >= 0) ? mask[row * Wc + t] : 0.0f;
    }
#pragma unroll
    for (int k = 0; k < 9; k++) {        // base-tap P rows (coalesced; row<=255 always)
        const int row = h + k / 3 - 2;
        sP[k * 256 + t] = (row >= 0) ? g_P[k * PIX + b * (Hc * Wc) + row * Wc + t]
                                     : 0.0f;
    }
    __syncthreads();

    // ---- single wave: 9 offset-path P gathers + 9 offset-mask gathers ----
    float Vo[9], pmoff[9];
#pragma unroll
    for (int k = 0; k < 9; k++) {
        const int ky = k / 3;
        const int kx = k - ky * 3;
        const int yb = h + ky - 1;
        const int xb = w + kx - 1;
        const bool inb = (yb >= 0) & (yb < Hc) & (xb >= 0) & (xb < Wc);
        const int yi = inb ? yb : 0;
        const int xi = inb ? xb : 0;

        const float2 off2 = *reinterpret_cast<const float2*>(&soff[t * 18 + 2 * k]);

        // offset-path final coords (diff==1 case): clip(yi+off, 0, 255) then floor
        const float yf = fminf(fmaxf((float)yi + off2.x, 0.0f), 255.0f);
        const float xf = fminf(fmaxf((float)xi + off2.y, 0.0f), 255.0f);
        const int y0 = (int)floorf(yf);
        const int x0 = (int)floorf(xf);
        Vo[k] = ((y0 >= 1) & (x0 >= 1))
                    ? Pbase[k * PIX + (y0 - 1) * Wc + (x0 - 1)] : 0.0f;

        // mask at offset point (padded coords, floor + clip to [0,257])
        int yo = (int)floorf((float)yi + off2.x);
        int xo = (int)floorf((float)xi + off2.y);
        yo = min(max(yo, 0), Hc + 1);
        xo = min(max(xo, 0), Wc + 1);
        pmoff[k] = ((yo >= 1) & (yo <= Hc) & (xo >= 1) & (xo <= Wc))
                       ? mask[(yo - 1) * Wc + (xo - 1)] : 0.0f;
    }

    // ---- select + sum (smem-only consumers) ----
    float acc = __ldg(bias);
#pragma unroll
    for (int k = 0; k < 9; k++) {
        const int ky = k / 3;
        const int kx = k - ky * 3;
        const int yb = h + ky - 1;
        const int xb = w + kx - 1;
        const bool base_ok = (yb >= 1) & (yb < Hc) & (xb >= 1) & (xb < Wc);
        const float pmask = base_ok ? smask[ky * 256 + (w + kx - 2)] : 0.0f;
        const float Vb    = base_ok ? sP[k * 256 + (w + kx - 2)] : 0.0f;
        acc += (pmask != pmoff[k]) ? Vo[k] : Vb;
    }

    out[pixbase + t] = acc;
}

} // namespace

extern "C" void kernel_launch(void* const* d_in, const int* in_sizes, int n_in,
                              void* d_out, int out_size)
{
    const float* input  = (const float*)d_in[0];   // [4,256,256,64]
    const float* mask   = (const float*)d_in[1];   // [1,256,256,1]
    const float* offset = (const float*)d_in[2];   // [4,256,256,18]
    const float* kern   = (const float*)d_in[3];   // [3,3,64,1]
    const float* bias   = (const float*)d_in[4];   // [1]
    float* out = (float*)d_out;

    dcn_phase1<<<PIX / P1_T, P1_T>>>(input, kern);
    dcn_phase2<<<PIX / P2_T, P2_T>>>(mask, offset, bias, out);
}